// round 1
// baseline (speedup 1.0000x reference)
#include <cuda_runtime.h>
#include <cstdint>
#include <cstddef>

#define NROWS 8192
#define FD 64
#define CJ 128
#define TILE_I 64
#define JSPLIT 8
#define NWARP 8
#define RW 8

typedef unsigned long long ull;

// scratch (static __device__ globals: allocation-free per harness rules)
__device__ float g_Wh[NROWS * FD];              // 2 MB
__device__ float g_s[NROWS];
__device__ float g_d[NROWS];
__device__ float g_pacc[JSPLIT][NROWS][FD];     // 16.8 MB partial O
__device__ float g_pl[JSPLIT][NROWS];           // partial row sums

// exp(t) on the FMA pipe (avoids MUFU bottleneck). Valid for any t, clamped
// to 2^[-126,126]. Magic-number round-to-nearest + degree-6 Taylor of e^y on
// |y| <= ln2/2: rel err ~1.2e-7.
__device__ __forceinline__ float fast_exp(float t) {
    float x = t * 1.4426950408889634f;           // log2(e)
    x = fminf(fmaxf(x, -126.0f), 126.0f);
    float c = x + 12582912.0f;                   // 1.5*2^23: round-to-nearest-int
    int   ic = __float_as_int(c);
    float xi = c - 12582912.0f;
    float f  = x - xi;                           // [-0.5, 0.5]
    float y  = f * 0.6931471805599453f;          // f*ln2
    float p = 1.3888889e-3f;
    p = fmaf(p, y, 8.3333333e-3f);
    p = fmaf(p, y, 4.1666667e-2f);
    p = fmaf(p, y, 1.6666667e-1f);
    p = fmaf(p, y, 0.5f);
    p = fmaf(p, y, 1.0f);
    p = fmaf(p, y, 1.0f);
    float sc = __int_as_float(((ic & 0x7FFFFF) - 0x400000 + 127) << 23);
    return p * sc;
}

// acc (f32x2 pair) += {w,w} * wh_pair  — packed dual-fp32 FMA (full-rate on sm_103a)
#define FFMA2S(accv, ws, whp)                                                  \
    asm("{\n\t.reg .b64 t;\n\tmov.b64 t, {%1, %1};\n\t"                        \
        "fma.rn.f32x2 %0, t, %2, %0;\n\t}"                                     \
        : "+l"(accv) : "f"(ws), "l"(whp))

// ---------------------------------------------------------------------------
// Kernel 1: Wh = X @ W  (+ s = Wh@a_src, d = Wh@a_dst fused)
// 64 rows per block, 256 threads: thread (r, fg) computes 16 features.
// ---------------------------------------------------------------------------
__global__ __launch_bounds__(256) void k_wh(const float* __restrict__ inp,
                                            const float* __restrict__ W,
                                            const float* __restrict__ a) {
    __shared__ float sIn[64 * 65];   // padded: bank-conflict-free row reads
    __shared__ float sW[64 * 64];
    __shared__ float sA[128];
    int tid = threadIdx.x;
    int i0  = blockIdx.x * 64;
    for (int idx = tid; idx < 4096; idx += 256) {
        int r = idx >> 6, k = idx & 63;
        sIn[r * 65 + k] = inp[i0 * 64 + idx];
        sW[idx] = W[idx];
    }
    if (tid < 128) sA[tid] = a[tid];
    __syncthreads();

    int r = tid >> 2, fg = tid & 3;
    float acc[16];
#pragma unroll
    for (int q = 0; q < 16; ++q) acc[q] = 0.f;
    const float4* sW4 = (const float4*)sW;
#pragma unroll 4
    for (int k = 0; k < 64; ++k) {
        float x = sIn[r * 65 + k];
#pragma unroll
        for (int q = 0; q < 4; ++q) {
            float4 wv = sW4[k * 16 + fg * 4 + q];
            acc[q * 4 + 0] = fmaf(x, wv.x, acc[q * 4 + 0]);
            acc[q * 4 + 1] = fmaf(x, wv.y, acc[q * 4 + 1]);
            acc[q * 4 + 2] = fmaf(x, wv.z, acc[q * 4 + 2]);
            acc[q * 4 + 3] = fmaf(x, wv.w, acc[q * 4 + 3]);
        }
    }
    int row = i0 + r;
    float ps = 0.f, pd = 0.f;
#pragma unroll
    for (int q = 0; q < 16; ++q) {
        ps = fmaf(acc[q], sA[fg * 16 + q], ps);
        pd = fmaf(acc[q], sA[64 + fg * 16 + q], pd);
    }
    float4* whp = (float4*)(g_Wh + row * 64 + fg * 16);
#pragma unroll
    for (int q = 0; q < 4; ++q)
        whp[q] = make_float4(acc[q * 4], acc[q * 4 + 1], acc[q * 4 + 2], acc[q * 4 + 3]);
    ps += __shfl_xor_sync(0xffffffffu, ps, 1, 4);
    ps += __shfl_xor_sync(0xffffffffu, ps, 2, 4);
    pd += __shfl_xor_sync(0xffffffffu, pd, 1, 4);
    pd += __shfl_xor_sync(0xffffffffu, pd, 2, 4);
    if (fg == 0) { g_s[row] = ps; g_d[row] = pd; }
}

// ---------------------------------------------------------------------------
// Kernel 2: fused mask + exp + P@Wh (no-max softmax: exp(e) fits fp32 here).
// Grid = 128 i-tiles x 8 j-splits. CTA: 256 thr / 8 warps, 8 rows per warp,
// 128-j chunks. Phase A: w into per-warp smem. Phase B: f32x2 packed GEMM.
// ---------------------------------------------------------------------------
#define SMEM_WH_BYTES (CJ * FD * 4)                        // 32768
#define SMEM_D_OFF    SMEM_WH_BYTES
#define SMEM_P_OFF    (SMEM_WH_BYTES + 512)                // 33280
#define SMEM_TOTAL    (SMEM_P_OFF + NWARP * CJ * RW * 4)   // 66048

__global__ __launch_bounds__(256, 3) void k_attn(const int* __restrict__ adj) {
    extern __shared__ char smem[];
    float* sWh  = (float*)smem;
    float* sD   = (float*)(smem + SMEM_D_OFF);
    int tid  = threadIdx.x;
    int wid  = tid >> 5, lane = tid & 31;
    float* sPmy = (float*)(smem + SMEM_P_OFF) + wid * CJ * RW;

    int itile  = blockIdx.x & 127;
    int sp     = blockIdx.x >> 7;
    int i0     = itile * TILE_I;
    int jbase0 = sp * (NROWS / JSPLIT);
    int row0   = i0 + wid * RW;

    float s[8];
#pragma unroll
    for (int r = 0; r < 8; ++r) s[r] = g_s[row0 + r];
    ull acc[8];
#pragma unroll
    for (int r = 0; r < 8; ++r) acc[r] = 0ULL;
    float lpart[8];
#pragma unroll
    for (int r = 0; r < 8; ++r) lpart[r] = 0.f;

    const ull* sWhU = (const ull*)sWh;

    for (int cc = 0; cc < (NROWS / JSPLIT) / CJ; ++cc) {   // 8 chunks
        int jb = jbase0 + cc * CJ;
        __syncthreads();
        // cooperative load of Wh chunk (128 x 64 f32 = 32 KB) + d chunk
        {
            const float4* src  = (const float4*)(g_Wh + (size_t)jb * FD);
            float4*       dst4 = (float4*)sWh;
#pragma unroll
            for (int q = 0; q < 8; ++q) dst4[tid + q * 256] = src[tid + q * 256];
            if (tid < CJ) sD[tid] = g_d[jb + tid];
        }
        __syncthreads();

        // ---- Phase A: weights w = adj ? exp(lrelu(s_i + d_j)) : 0 ----
        const int* adjp = adj + (size_t)row0 * NROWS + jb;
#pragma unroll
        for (int g = 0; g < 4; ++g) {
            int   jl = g * 32 + lane;
            float dj = sD[jl];
            float w8[8];
#pragma unroll
            for (int r = 0; r < 8; ++r) {
                int   av = __ldg(adjp + (size_t)r * NROWS + jl);
                float e  = s[r] + dj;
                e        = fmaxf(e, 0.2f * e);      // leaky relu
                float wv = fast_exp(e);
                wv       = (av > 0) ? wv : 0.0f;
                lpart[r] += wv;
                w8[r] = wv;
            }
            float4* pd4 = (float4*)(sPmy + jl * 8);
            pd4[0] = make_float4(w8[0], w8[1], w8[2], w8[3]);
            pd4[1] = make_float4(w8[4], w8[5], w8[6], w8[7]);
        }
        __syncwarp();

        // ---- Phase B: acc(8 rows x 2 feats, f32x2) += P * Wh ----
#pragma unroll 8
        for (int jl = 0; jl < CJ; ++jl) {
            ull    wh = sWhU[jl * 32 + lane];                 // feats 2l,2l+1
            float4 pa = *(const float4*)(sPmy + jl * 8);      // broadcast
            float4 pb = *(const float4*)(sPmy + jl * 8 + 4);  // broadcast
            FFMA2S(acc[0], pa.x, wh);
            FFMA2S(acc[1], pa.y, wh);
            FFMA2S(acc[2], pa.z, wh);
            FFMA2S(acc[3], pa.w, wh);
            FFMA2S(acc[4], pb.x, wh);
            FFMA2S(acc[5], pb.y, wh);
            FFMA2S(acc[6], pb.z, wh);
            FFMA2S(acc[7], pb.w, wh);
        }
    }

    // epilogue: write split-partials
#pragma unroll
    for (int r = 0; r < 8; ++r) {
        float lr = lpart[r];
#pragma unroll
        for (int o = 16; o > 0; o >>= 1) lr += __shfl_xor_sync(0xffffffffu, lr, o);
        float lo, hi;
        asm("mov.b64 {%0, %1}, %2;" : "=f"(lo), "=f"(hi) : "l"(acc[r]));
        int row = row0 + r;
        *(float2*)(&g_pacc[sp][row][2 * lane]) = make_float2(lo, hi);
        if (lane == 0) g_pl[sp][row] = lr;
    }
}

// ---------------------------------------------------------------------------
// Kernel 3: combine j-split partials, normalize, ELU
// ---------------------------------------------------------------------------
__global__ __launch_bounds__(256) void k_final(float* __restrict__ out) {
    int idx = blockIdx.x * 256 + threadIdx.x;   // 262144 threads
    int i = idx >> 5, l = idx & 31;
    float a0 = 0.f, a1 = 0.f, ls = 0.f;
#pragma unroll
    for (int sp = 0; sp < JSPLIT; ++sp) {
        float2 p = *(const float2*)(&g_pacc[sp][i][2 * l]);
        a0 += p.x; a1 += p.y;
        ls += g_pl[sp][i];
    }
    float inv = 1.0f / ls;
    a0 *= inv; a1 *= inv;
    a0 = (a0 > 0.f) ? a0 : (fast_exp(a0) - 1.f);   // elu
    a1 = (a1 > 0.f) ? a1 : (fast_exp(a1) - 1.f);
    *(float2*)(out + i * 64 + 2 * l) = make_float2(a0, a1);
}

extern "C" void kernel_launch(void* const* d_in, const int* in_sizes, int n_in,
                              void* d_out, int out_size) {
    const float* inp = (const float*)d_in[0];
    const int*   adj = (const int*)d_in[1];
    const float* W   = (const float*)d_in[2];
    const float* a   = (const float*)d_in[3];
    float*       out = (float*)d_out;

    cudaFuncSetAttribute(k_attn, cudaFuncAttributeMaxDynamicSharedMemorySize,
                         SMEM_TOTAL);

    k_wh<<<NROWS / 64, 256>>>(inp, W, a);
    k_attn<<<JSPLIT * (NROWS / TILE_I), 256, SMEM_TOTAL>>>(adj);
    k_final<<<(NROWS * 32) / 256, 256>>>(out);
}

// round 2
// speedup vs baseline: 1.1075x; 1.1075x over previous
#include <cuda_runtime.h>
#include <cstdint>
#include <cstddef>

#define NROWS 8192
#define FD 64
#define CJ 128
#define TILE_I 64
#define JSPLIT 8
#define NWARP 8
#define RW 8

typedef unsigned long long ull;

// scratch (static __device__ globals: allocation-free per harness rules)
__device__ float g_Wh[NROWS * FD];              // 2 MB
__device__ float g_s[NROWS];
__device__ float g_d[NROWS];
__device__ float g_es[NROWS];                   // exp(s)
__device__ float g_fs[NROWS];                   // exp(0.2 s)
__device__ float g_ed[NROWS];                   // exp(d)
__device__ float g_fd[NROWS];                   // exp(0.2 d)
__device__ float g_pacc[JSPLIT][NROWS][FD];     // 16.8 MB partial O
__device__ float g_pl[JSPLIT][NROWS];           // partial row sums

// exp(t) on the FMA pipe. Magic-number round + degree-6 Taylor, rel err ~1e-7.
__device__ __forceinline__ float fast_exp(float t) {
    float x = t * 1.4426950408889634f;           // log2(e)
    x = fminf(fmaxf(x, -126.0f), 126.0f);
    float c = x + 12582912.0f;                   // 1.5*2^23
    int   ic = __float_as_int(c);
    float xi = c - 12582912.0f;
    float f  = x - xi;
    float y  = f * 0.6931471805599453f;
    float p = 1.3888889e-3f;
    p = fmaf(p, y, 8.3333333e-3f);
    p = fmaf(p, y, 4.1666667e-2f);
    p = fmaf(p, y, 1.6666667e-1f);
    p = fmaf(p, y, 0.5f);
    p = fmaf(p, y, 1.0f);
    p = fmaf(p, y, 1.0f);
    float sc = __int_as_float(((ic & 0x7FFFFF) - 0x400000 + 127) << 23);
    return p * sc;
}

// acc (f32x2 pair) += p_pair * wh_pair   (packed dual-fp32 FMA)
#define FFMA2(accv, pv, whv)                                                   \
    asm("fma.rn.f32x2 %0, %1, %2, %0;" : "+l"(accv) : "l"(pv), "l"(whv))

// ---------------------------------------------------------------------------
// Kernel 1: Wh = X@W, fused s/d = Wh@a_src / Wh@a_dst, fused exp factor tables.
// 16 rows per block, 128 threads: thread (r, fg) computes 8 features. grid=512.
// ---------------------------------------------------------------------------
__global__ __launch_bounds__(128) void k_wh(const float* __restrict__ inp,
                                            const float* __restrict__ W,
                                            const float* __restrict__ a) {
    __shared__ float sIn[16 * 65];
    __shared__ float sW[64 * 64];
    __shared__ float sA[128];
    int tid = threadIdx.x;
    int i0  = blockIdx.x * 16;
    for (int idx = tid; idx < 1024; idx += 128) {
        int r = idx >> 6, k = idx & 63;
        sIn[r * 65 + k] = inp[i0 * 64 + idx];
    }
    const float4* W4 = (const float4*)W;
    float4* sW4w = (float4*)sW;
#pragma unroll
    for (int q = 0; q < 8; ++q) sW4w[tid + q * 128] = W4[tid + q * 128];
    if (tid < 128) sA[tid] = a[tid];
    __syncthreads();

    int r = tid >> 3, fg = tid & 7;
    float acc[8];
#pragma unroll
    for (int q = 0; q < 8; ++q) acc[q] = 0.f;
    const float4* sW4 = (const float4*)sW;
#pragma unroll 8
    for (int k = 0; k < 64; ++k) {
        float x = sIn[r * 65 + k];
        float4 w0 = sW4[k * 16 + fg * 2 + 0];
        float4 w1 = sW4[k * 16 + fg * 2 + 1];
        acc[0] = fmaf(x, w0.x, acc[0]);
        acc[1] = fmaf(x, w0.y, acc[1]);
        acc[2] = fmaf(x, w0.z, acc[2]);
        acc[3] = fmaf(x, w0.w, acc[3]);
        acc[4] = fmaf(x, w1.x, acc[4]);
        acc[5] = fmaf(x, w1.y, acc[5]);
        acc[6] = fmaf(x, w1.z, acc[6]);
        acc[7] = fmaf(x, w1.w, acc[7]);
    }
    int row = i0 + r;
    float ps = 0.f, pd = 0.f;
#pragma unroll
    for (int q = 0; q < 8; ++q) {
        ps = fmaf(acc[q], sA[fg * 8 + q], ps);
        pd = fmaf(acc[q], sA[64 + fg * 8 + q], pd);
    }
    float4* whp = (float4*)(g_Wh + row * 64 + fg * 8);
    whp[0] = make_float4(acc[0], acc[1], acc[2], acc[3]);
    whp[1] = make_float4(acc[4], acc[5], acc[6], acc[7]);
#pragma unroll
    for (int o = 1; o < 8; o <<= 1) {
        ps += __shfl_xor_sync(0xffffffffu, ps, o, 8);
        pd += __shfl_xor_sync(0xffffffffu, pd, o, 8);
    }
    if (fg == 0) {
        float sc = fminf(fmaxf(ps, -87.f), 80.f);
        float dc = fminf(fmaxf(pd, -87.f), 80.f);
        g_s[row]  = ps;
        g_d[row]  = pd;
        g_es[row] = fast_exp(sc);
        g_fs[row] = fast_exp(0.2f * sc);
        g_ed[row] = fast_exp(dc);
        g_fd[row] = fast_exp(0.2f * dc);
    }
}

// ---------------------------------------------------------------------------
// Kernel 2: fused mask + factorized-exp softmax weights + P@Wh (f32x2 packed).
// Grid = 128 i-tiles x 8 j-splits. 256 thr / 8 warps, 8 rows/warp, CJ=128.
// ---------------------------------------------------------------------------
#define SMEM_WH_BYTES (CJ * FD * 4)                        // 32768
#define SMEM_D_OFF    SMEM_WH_BYTES                        // 3*128 floats = 1536B
#define SMEM_P_OFF    (SMEM_WH_BYTES + 1536)               // 34304
#define SMEM_TOTAL    (SMEM_P_OFF + NWARP * CJ * RW * 4)   // 67072

__global__ __launch_bounds__(256, 3) void k_attn(const int* __restrict__ adj) {
    extern __shared__ char smem[];
    float* sWh = (float*)smem;
    float* sD  = (float*)(smem + SMEM_D_OFF);          // d
    float* sED = sD + CJ;                              // exp(d)
    float* sFD = sD + 2 * CJ;                          // exp(0.2 d)
    int tid  = threadIdx.x;
    int wid  = tid >> 5, lane = tid & 31;
    float* sPmy = (float*)(smem + SMEM_P_OFF) + wid * CJ * RW;

    int itile  = blockIdx.x & 127;
    int sp     = blockIdx.x >> 7;
    int i0     = itile * TILE_I;
    int jbase0 = sp * (NROWS / JSPLIT);
    int row0   = i0 + wid * RW;

    float s[8], Es[8], Fs[8];
#pragma unroll
    for (int r = 0; r < 8; ++r) {
        s[r]  = g_s[row0 + r];
        Es[r] = g_es[row0 + r];
        Fs[r] = g_fs[row0 + r];
    }
    ull acc[8];
#pragma unroll
    for (int r = 0; r < 8; ++r) acc[r] = 0ULL;
    float lpart[8];
#pragma unroll
    for (int r = 0; r < 8; ++r) lpart[r] = 0.f;

    for (int cc = 0; cc < (NROWS / JSPLIT) / CJ; ++cc) {   // 8 chunks
        int jb = jbase0 + cc * CJ;
        __syncthreads();
        {   // cooperative load of Wh chunk (32 KB) + d/ed/fd chunk
            const float4* src  = (const float4*)(g_Wh + (size_t)jb * FD);
            float4*       dst4 = (float4*)sWh;
#pragma unroll
            for (int q = 0; q < 8; ++q) dst4[tid + q * 256] = src[tid + q * 256];
            if (tid < CJ) {
                sD[tid]  = g_d[jb + tid];
                sFD[tid] = g_fd[jb + tid];
            } else if (tid < 2 * CJ) {
                sED[tid - CJ] = g_ed[jb + tid - CJ];
            }
        }
        __syncthreads();

        // ---- Phase A: w = adj ? ((s+d>0) ? Es*Ed : Fs*Fd) : 0 ----
        const int* adjp = adj + (size_t)row0 * NROWS + jb;
#pragma unroll
        for (int g = 0; g < 4; ++g) {
            int   jl  = g * 32 + lane;
            float dj  = sD[jl];
            float edj = sED[jl];
            float fdj = sFD[jl];
            float w8[8];
#pragma unroll
            for (int r = 0; r < 8; ++r) {
                int   av  = __ldg(adjp + (size_t)r * NROWS + jl);
                float t   = s[r] + dj;
                bool  pos = t > 0.f;
                float ea  = pos ? Es[r] : Fs[r];
                float eb  = pos ? edj : fdj;
                ea        = (av > 0) ? ea : 0.f;
                float w   = ea * eb;
                lpart[r] += w;
                w8[r] = w;
            }
            float4* pd4 = (float4*)(sPmy + jl * 8);
            pd4[0] = make_float4(w8[0], w8[1], w8[2], w8[3]);
            pd4[1] = make_float4(w8[4], w8[5], w8[6], w8[7]);
        }
        __syncwarp();

        // ---- Phase B: row-pair-packed f32x2 GEMM  acc += P * Wh ----
        // acc[h*4+p] holds rows (2p,2p+1), feature h*32+lane.
#pragma unroll 8
        for (int jl = 0; jl < CJ; ++jl) {
            ulonglong2 pA = *(const ulonglong2*)(sPmy + jl * 8);      // {w0,w1},{w2,w3}
            ulonglong2 pB = *(const ulonglong2*)(sPmy + jl * 8 + 4);  // {w4,w5},{w6,w7}
            float wh0 = sWh[jl * 64 + lane];
            float wh1 = sWh[jl * 64 + 32 + lane];
            ull whp0, whp1;
            asm("mov.b64 %0, {%1,%1};" : "=l"(whp0) : "f"(wh0));
            asm("mov.b64 %0, {%1,%1};" : "=l"(whp1) : "f"(wh1));
            FFMA2(acc[0], pA.x, whp0);
            FFMA2(acc[1], pA.y, whp0);
            FFMA2(acc[2], pB.x, whp0);
            FFMA2(acc[3], pB.y, whp0);
            FFMA2(acc[4], pA.x, whp1);
            FFMA2(acc[5], pA.y, whp1);
            FFMA2(acc[6], pB.x, whp1);
            FFMA2(acc[7], pB.y, whp1);
        }
    }

    // epilogue: write split-partials
#pragma unroll
    for (int r = 0; r < 8; ++r) {
        float lr = lpart[r];
#pragma unroll
        for (int o = 16; o > 0; o >>= 1) lr += __shfl_xor_sync(0xffffffffu, lr, o);
        if (lane == 0) g_pl[sp][row0 + r] = lr;
    }
#pragma unroll
    for (int p = 0; p < 4; ++p) {
        float lo0, hi0, lo1, hi1;
        asm("mov.b64 {%0, %1}, %2;" : "=f"(lo0), "=f"(hi0) : "l"(acc[p]));
        asm("mov.b64 {%0, %1}, %2;" : "=f"(lo1), "=f"(hi1) : "l"(acc[4 + p]));
        int ra = row0 + 2 * p, rb = ra + 1;
        g_pacc[sp][ra][lane]      = lo0;
        g_pacc[sp][ra][lane + 32] = lo1;
        g_pacc[sp][rb][lane]      = hi0;
        g_pacc[sp][rb][lane + 32] = hi1;
    }
}

// ---------------------------------------------------------------------------
// Kernel 3: combine j-split partials, normalize, ELU
// ---------------------------------------------------------------------------
__global__ __launch_bounds__(256) void k_final(float* __restrict__ out) {
    int idx = blockIdx.x * 256 + threadIdx.x;   // 262144 threads
    int i = idx >> 5, l = idx & 31;
    float a0 = 0.f, a1 = 0.f, ls = 0.f;
#pragma unroll
    for (int sp = 0; sp < JSPLIT; ++sp) {
        float2 p = *(const float2*)(&g_pacc[sp][i][2 * l]);
        a0 += p.x; a1 += p.y;
        ls += g_pl[sp][i];
    }
    float inv = 1.0f / ls;
    a0 *= inv; a1 *= inv;
    a0 = (a0 > 0.f) ? a0 : (fast_exp(a0) - 1.f);   // elu
    a1 = (a1 > 0.f) ? a1 : (fast_exp(a1) - 1.f);
    *(float2*)(out + i * 64 + 2 * l) = make_float2(a0, a1);
}

extern "C" void kernel_launch(void* const* d_in, const int* in_sizes, int n_in,
                              void* d_out, int out_size) {
    const float* inp = (const float*)d_in[0];
    const int*   adj = (const int*)d_in[1];
    const float* W   = (const float*)d_in[2];
    const float* a   = (const float*)d_in[3];
    float*       out = (float*)d_out;

    cudaFuncSetAttribute(k_attn, cudaFuncAttributeMaxDynamicSharedMemorySize,
                         SMEM_TOTAL);

    k_wh<<<NROWS / 16, 128>>>(inp, W, a);
    k_attn<<<JSPLIT * (NROWS / TILE_I), 256, SMEM_TOTAL>>>(adj);
    k_final<<<(NROWS * 32) / 256, 256>>>(out);
}